// round 11
// baseline (speedup 1.0000x reference)
#include <cuda_runtime.h>
#include <cuda_bf16.h>
#include <cstdint>

// ---------------- problem constants ----------------
#define HIDDEN      128
#define NUM_RADIAL  6
#define OUT_EMB     256
#define MAX_NODES   50000
#define MAX_EDGES   1600000

#define AS_STRIDE   264      // ≡8 mod 32 → conflict-free LDS.64 A fragments
#define WS_STRIDE   40       // ≡8 mod 32 → conflict-free LDS.64 B fragments

// gather pipeline
#define G_DEPTH 3
#define G_EPB   4

// ---------------- device scratch ----------------
__device__ float g_h[(size_t)MAX_NODES * HIDDEN];
__device__ float g_w[HIDDEN * OUT_EMB + 3 * OUT_EMB * OUT_EMB];   // tf32-rounded, k-pair permuted
__device__ int   g_cnt[MAX_NODES];
__device__ int   g_start[MAX_NODES];
__device__ int   g_cursor[MAX_NODES];
__device__ int   g_eid[MAX_EDGES];
__device__ int   g_blksum[64];

// ---------------- helpers ----------------
__device__ __forceinline__ uint32_t smem_u32(const void* p) {
    uint32_t a;
    asm("{ .reg .u64 t; cvta.to.shared.u64 t, %1; cvt.u32.u64 %0, t; }" : "=r"(a) : "l"(p));
    return a;
}
__device__ __forceinline__ uint32_t f2tf(float x) {
    uint32_t r; asm("cvt.rna.tf32.f32 %0, %1;" : "=r"(r) : "f"(x)); return r;
}
__device__ __forceinline__ float f2tf_f(float x) { return __uint_as_float(f2tf(x)); }
// k-pair interleave within each 8-col group: logical o -> phys 2*(o&3) + (o>>2)
__device__ __forceinline__ int phys8(int col) {
    return (col & ~7) + 2 * (col & 3) + ((col >> 2) & 1);
}
__device__ __forceinline__ void mma8(float* d, const uint32_t* a, uint32_t b0, uint32_t b1) {
    asm volatile("mma.sync.aligned.m16n8k8.row.col.f32.tf32.tf32.f32 "
                 "{%0,%1,%2,%3}, {%4,%5,%6,%7}, {%8,%9}, {%0,%1,%2,%3};"
                 : "+f"(d[0]), "+f"(d[1]), "+f"(d[2]), "+f"(d[3])
                 : "r"(a[0]), "r"(a[1]), "r"(a[2]), "r"(a[3]), "r"(b0), "r"(b1));
}
__device__ __forceinline__ void cp16(uint32_t s, const float* g) {
    asm volatile("cp.async.cg.shared.global [%0], [%1], 16;" :: "r"(s), "l"(g));
}
__device__ __forceinline__ void cp8(uint32_t s, const float* g) {
    asm volatile("cp.async.ca.shared.global [%0], [%1], 8;" :: "r"(s), "l"(g));
}
#define CP_COMMIT() asm volatile("cp.async.commit_group;")
#define CP_WAIT(n)  asm volatile("cp.async.wait_group %0;" :: "n"(n))

// ================= init: zero cnt + tf32-round & permute weights =================
__global__ void __launch_bounds__(256) init_kernel(const float* __restrict__ W_up,
                                                   const float* __restrict__ lins_w, int N) {
    int gid = blockIdx.x * 256 + threadIdx.x;
    if (gid < N) g_cnt[gid] = 0;
    const int NW_UP = HIDDEN * OUT_EMB;
    const int NW_ALL = NW_UP + 3 * OUT_EMB * OUT_EMB;
    if (gid < NW_UP) {
        int n = gid >> 7, k = gid & 127;                 // W_up [256][128]
        g_w[n * HIDDEN + phys8(k)] = f2tf_f(W_up[gid]);
    } else if (gid < NW_ALL) {
        int g2 = gid - NW_UP;
        int row = g2 >> 8, k = g2 & 255;                 // lins [768][256]
        g_w[NW_UP + row * OUT_EMB + phys8(k)] = f2tf_f(lins_w[g2]);
    }
}

__global__ void __launch_bounds__(256) hist_kernel(const int* __restrict__ ei, int E, int N) {
    int e = blockIdx.x * 256 + threadIdx.x;
    if (e < E) {
        int node = __ldg(ei + e);
        if (node >= 0 && node < N) atomicAdd(&g_cnt[node], 1);
    }
}

__global__ void __launch_bounds__(1024) scan1_kernel(int N) {
    __shared__ int sw[32];
    int tid = threadIdx.x;
    int i = blockIdx.x * 1024 + tid;
    int v = (i < N) ? g_cnt[i] : 0;
#pragma unroll
    for (int o = 16; o; o >>= 1) v += __shfl_xor_sync(0xffffffffu, v, o);
    if ((tid & 31) == 0) sw[tid >> 5] = v;
    __syncthreads();
    if (tid < 32) {
        int s = sw[tid];
#pragma unroll
        for (int o = 16; o; o >>= 1) s += __shfl_xor_sync(0xffffffffu, s, o);
        if (tid == 0) g_blksum[blockIdx.x] = s;
    }
}

__global__ void __launch_bounds__(1024) scan2_kernel(int N, int nb) {
    __shared__ int swarp[32];
    __shared__ int sb2[2];
    int tid = threadIdx.x, lane = tid & 31, wid = tid >> 5;

    if (tid < 64) {
        int c = (tid < nb && tid < blockIdx.x) ? g_blksum[tid] : 0;
#pragma unroll
        for (int o = 16; o; o >>= 1) c += __shfl_xor_sync(0xffffffffu, c, o);
        if (lane == 0) sb2[wid] = c;
    }

    int i = blockIdx.x * 1024 + tid;
    int v = (i < N) ? g_cnt[i] : 0;
    int xi = v;
#pragma unroll
    for (int o = 1; o < 32; o <<= 1) {
        int y = __shfl_up_sync(0xffffffffu, xi, o);
        if (lane >= o) xi += y;
    }
    if (lane == 31) swarp[wid] = xi;
    __syncthreads();
    if (wid == 0) {
        int s = swarp[lane];
#pragma unroll
        for (int o = 1; o < 32; o <<= 1) {
            int y = __shfl_up_sync(0xffffffffu, s, o);
            if (lane >= o) s += y;
        }
        swarp[lane] = s;
    }
    __syncthreads();
    int woff = (wid == 0) ? 0 : swarp[wid - 1];
    int excl = woff + xi - v;
    int boff = sb2[0] + sb2[1];
    if (i < N) { g_start[i] = boff + excl; g_cursor[i] = boff + excl; }
}

__global__ void __launch_bounds__(256) scatter_kernel(const int* __restrict__ ei, int E, int N) {
    int e = blockIdx.x * 256 + threadIdx.x;
    if (e < E) {
        int node = __ldg(ei + e);
        if (node >= 0 && node < N) {
            int pos = atomicAdd(&g_cursor[node], 1);
            g_eid[pos] = e;
        }
    }
}

// ================= gather: cp.async smem pipeline, 1 warp/node =================
__global__ void __launch_bounds__(256) gather_kernel(const float* __restrict__ x,
                                                     const float* __restrict__ rbf,
                                                     const float* __restrict__ W_rbf,
                                                     int N) {
    extern __shared__ char gsm[];
    const int tid = threadIdx.x;
    const int lane = tid & 31;
    const int w = tid >> 5;
    const int node = blockIdx.x * 8 + w;

    char* xw = gsm + w * (G_DEPTH * G_EPB * 512);
    float* rw = (float*)(gsm + 8 * (G_DEPTH * G_EPB * 512) + w * (G_DEPTH * G_EPB * 32));
    const uint32_t xs_base = smem_u32(xw);
    const uint32_t rs_base = smem_u32(rw);

    float4 wc[NUM_RADIAL];
#pragma unroll
    for (int r = 0; r < NUM_RADIAL; r++) {
        wc[r].x = __ldg(W_rbf + (lane * 4 + 0) * NUM_RADIAL + r);
        wc[r].y = __ldg(W_rbf + (lane * 4 + 1) * NUM_RADIAL + r);
        wc[r].z = __ldg(W_rbf + (lane * 4 + 2) * NUM_RADIAL + r);
        wc[r].w = __ldg(W_rbf + (lane * 4 + 3) * NUM_RADIAL + r);
    }

    int start = 0, cnt = 0;
    if (node < N) { start = __ldg(&g_start[node]); cnt = __ldg(&g_cnt[node]); }

    float4 acc = make_float4(0.f, 0.f, 0.f, 0.f);
    const int nb = (cnt + G_EPB - 1) / G_EPB;
    int e_l = 0;

    for (int b = 0; b < nb + 2; b++) {
        if (b < nb) {
            if ((b & 7) == 0) {
                int idx = b * G_EPB + lane;
                e_l = (idx < cnt) ? __ldg(g_eid + start + idx) : 0;
            }
            const int d = b % G_DEPTH;
            const int sh = (b & 7) * G_EPB;
#pragma unroll
            for (int i = 0; i < G_EPB; i++) {
                int e = __shfl_sync(0xffffffffu, e_l, sh + i);
                cp16(xs_base + (d * G_EPB + i) * 512 + lane * 16,
                     x + (size_t)e * HIDDEN + lane * 4);
                if (lane < 3)
                    cp8(rs_base + ((d * G_EPB + i) * 8 + lane * 2) * 4,
                        rbf + (size_t)e * NUM_RADIAL + lane * 2);
            }
        }
        CP_COMMIT();
        if (b >= 2) {
            CP_WAIT(2);
            __syncwarp();
            const int cb = b - 2;
            const int d = cb % G_DEPTH;
            const int ebase = cb * G_EPB;
#pragma unroll
            for (int i = 0; i < G_EPB; i++) {
                if (ebase + i < cnt) {
                    const float* rp = rw + (d * G_EPB + i) * 8;
                    float4 xv = *(const float4*)(xw + (d * G_EPB + i) * 512 + lane * 16);
                    float r0 = rp[0], r1 = rp[1], r2 = rp[2];
                    float r3 = rp[3], r4 = rp[4], r5 = rp[5];
                    float4 p;
                    p.x = r0 * wc[0].x; p.y = r0 * wc[0].y; p.z = r0 * wc[0].z; p.w = r0 * wc[0].w;
                    p.x = fmaf(r1, wc[1].x, p.x); p.y = fmaf(r1, wc[1].y, p.y);
                    p.z = fmaf(r1, wc[1].z, p.z); p.w = fmaf(r1, wc[1].w, p.w);
                    p.x = fmaf(r2, wc[2].x, p.x); p.y = fmaf(r2, wc[2].y, p.y);
                    p.z = fmaf(r2, wc[2].z, p.z); p.w = fmaf(r2, wc[2].w, p.w);
                    p.x = fmaf(r3, wc[3].x, p.x); p.y = fmaf(r3, wc[3].y, p.y);
                    p.z = fmaf(r3, wc[3].z, p.z); p.w = fmaf(r3, wc[3].w, p.w);
                    p.x = fmaf(r4, wc[4].x, p.x); p.y = fmaf(r4, wc[4].y, p.y);
                    p.z = fmaf(r4, wc[4].z, p.z); p.w = fmaf(r4, wc[4].w, p.w);
                    p.x = fmaf(r5, wc[5].x, p.x); p.y = fmaf(r5, wc[5].y, p.y);
                    p.z = fmaf(r5, wc[5].z, p.z); p.w = fmaf(r5, wc[5].w, p.w);
                    acc.x = fmaf(p.x, xv.x, acc.x); acc.y = fmaf(p.y, xv.y, acc.y);
                    acc.z = fmaf(p.z, xv.z, acc.z); acc.w = fmaf(p.w, xv.w, acc.w);
                }
            }
        }
    }

    if (node < N)
        *(float4*)(g_h + (size_t)node * HIDDEN + lane * 4) = acc;
}

// ================= MLP via mma.sync tf32: 128-row tiles, LDS.64 fragments =================
template<int K, int MODE>
__device__ __forceinline__ void do_layer(float* __restrict__ As,
                                         const float* __restrict__ W0s,
                                         const float* __restrict__ W1s,
                                         uint32_t w0a, uint32_t w1a,
                                         const float* __restrict__ Wg,
                                         const float* __restrict__ bias,
                                         const float* __restrict__ wout,
                                         float* __restrict__ fpart,
                                         int wm, int wn, int lane, int tid) {
    constexpr int NC = K / 32;
    float d[2][8][4];
#pragma unroll
    for (int m = 0; m < 2; m++)
#pragma unroll
        for (int n = 0; n < 8; n++)
#pragma unroll
            for (int j = 0; j < 4; j++) d[m][n][j] = 0.f;

    {
#pragma unroll
        for (int i = 0; i < 4; i++) {
            int idx = tid + i * 512;
            int row = idx >> 3, q = idx & 7;
            cp16(w0a + (uint32_t)(row * WS_STRIDE + q * 4) * 4, Wg + (size_t)row * K + q * 4);
        }
        CP_COMMIT();
    }

    for (int c = 0; c < NC; c++) {
        __syncthreads();
        if (c + 1 < NC) {
            uint32_t na = ((c + 1) & 1) ? w1a : w0a;
#pragma unroll
            for (int i = 0; i < 4; i++) {
                int idx = tid + i * 512;
                int row = idx >> 3, q = idx & 7;
                cp16(na + (uint32_t)(row * WS_STRIDE + q * 4) * 4,
                     Wg + (size_t)row * K + (c + 1) * 32 + q * 4);
            }
            CP_COMMIT();
            CP_WAIT(1);
        } else {
            CP_WAIT(0);
        }
        __syncthreads();

        const float* Ws = (c & 1) ? W1s : W0s;
        const int kb0 = c * 32;
#pragma unroll
        for (int k8 = 0; k8 < 4; k8++) {
            const int kb = kb0 + k8 * 8;
            uint32_t ah[2][4];
#pragma unroll
            for (int m = 0; m < 2; m++) {
                int r = wm * 32 + m * 16 + (lane >> 2);
                const float* ap = As + r * AS_STRIDE + kb + 2 * (lane & 3);
                float2 la = *(const float2*)ap;                       // (r, k), (r, k+4)
                float2 lb = *(const float2*)(ap + 8 * AS_STRIDE);     // (r+8, k), (r+8, k+4)
                ah[m][0] = __float_as_uint(la.x);
                ah[m][1] = __float_as_uint(lb.x);
                ah[m][2] = __float_as_uint(la.y);
                ah[m][3] = __float_as_uint(lb.y);
            }
#pragma unroll
            for (int n = 0; n < 8; n++) {
                int coln = wn * 64 + n * 8 + (lane >> 2);
                float2 wb = *(const float2*)(Ws + coln * WS_STRIDE + k8 * 8 + 2 * (lane & 3));
                uint32_t b0 = __float_as_uint(wb.x);
                uint32_t b1 = __float_as_uint(wb.y);
#pragma unroll
                for (int m = 0; m < 2; m++)
                    mma8(d[m][n], ah[m], b0, b1);
            }
        }
    }

    if (MODE != 2) {
        __syncthreads();
#pragma unroll
        for (int m = 0; m < 2; m++) {
            int r = wm * 32 + m * 16 + (lane >> 2);
#pragma unroll
            for (int n = 0; n < 8; n++) {
                int col = wn * 64 + n * 8 + (lane & 3) * 2;
                float v0 = d[m][n][0], v1 = d[m][n][1];
                float v2 = d[m][n][2], v3 = d[m][n][3];
                if (MODE == 1) {
                    float b0 = bias[col], b1 = bias[col + 1];
                    v0 = fmaxf(v0 + b0, 0.f); v1 = fmaxf(v1 + b1, 0.f);
                    v2 = fmaxf(v2 + b0, 0.f); v3 = fmaxf(v3 + b1, 0.f);
                }
                v0 = f2tf_f(v0); v1 = f2tf_f(v1); v2 = f2tf_f(v2); v3 = f2tf_f(v3);
                int p0 = phys8(col), p1 = phys8(col + 1);
                As[r * AS_STRIDE + p0]       = v0;
                As[r * AS_STRIDE + p1]       = v1;
                As[(r + 8) * AS_STRIDE + p0] = v2;
                As[(r + 8) * AS_STRIDE + p1] = v3;
            }
        }
        __syncthreads();
    } else {
        float s[2][2] = {{0.f, 0.f}, {0.f, 0.f}};
#pragma unroll
        for (int m = 0; m < 2; m++)
#pragma unroll
            for (int n = 0; n < 8; n++) {
                int col = wn * 64 + n * 8 + (lane & 3) * 2;
                float b0 = bias[col], b1 = bias[col + 1];
                float w0 = wout[col], w1 = wout[col + 1];
                float v0 = fmaxf(d[m][n][0] + b0, 0.f);
                float v1 = fmaxf(d[m][n][1] + b1, 0.f);
                float v2 = fmaxf(d[m][n][2] + b0, 0.f);
                float v3 = fmaxf(d[m][n][3] + b1, 0.f);
                s[m][0] = fmaf(v0, w0, fmaf(v1, w1, s[m][0]));
                s[m][1] = fmaf(v2, w0, fmaf(v3, w1, s[m][1]));
            }
#pragma unroll
        for (int m = 0; m < 2; m++)
#pragma unroll
            for (int h = 0; h < 2; h++) {
                float v = s[m][h];
                v += __shfl_xor_sync(0xffffffffu, v, 1);
                v += __shfl_xor_sync(0xffffffffu, v, 2);
                s[m][h] = v;
            }
        if ((lane & 3) == 0) {
            int rbase = wm * 32 + (lane >> 2);
            fpart[wn * 128 + rbase]      = s[0][0];
            fpart[wn * 128 + rbase + 8]  = s[0][1];
            fpart[wn * 128 + rbase + 16] = s[1][0];
            fpart[wn * 128 + rbase + 24] = s[1][1];
        }
    }
}

// smem float offsets
#define F_AS    0                              // 128*264 = 33792
#define F_W0    33792                          // 256*40  = 10240
#define F_W1    (33792 + 10240)
#define F_BIAS  (33792 + 2 * 10240)            // 768
#define F_WOUT  (F_BIAS + 768)                 // 256
#define F_FPART (F_WOUT + 256)                 // 512
#define F_TOTAL (F_FPART + 512)                // 55808 floats = 223232 B

__global__ void __launch_bounds__(512, 1) mlp_kernel(const float* __restrict__ lins_b,
                                                     const float* __restrict__ W_out,
                                                     float* __restrict__ out, int N) {
    extern __shared__ float smem[];
    float* As    = smem + F_AS;
    float* W0s   = smem + F_W0;
    float* W1s   = smem + F_W1;
    float* sbias = smem + F_BIAS;
    float* swout = smem + F_WOUT;
    float* fpart = smem + F_FPART;
    uint32_t w0a = smem_u32(W0s), w1a = smem_u32(W1s);

    const int tid = threadIdx.x;
    const int lane = tid & 31;
    const int wid = tid >> 5;
    const int wm = wid & 3;
    const int wn = wid >> 2;
    const int rowBase = blockIdx.x * 128;

    for (int t = tid; t < 768; t += 512) sbias[t] = lins_b[t];
    if (tid < 256) swout[tid] = W_out[tid];

    // load A (g_h[128 rows x 128 cols]), tf32-round, k-pair permuted store
#pragma unroll
    for (int i = 0; i < 8; i++) {
        int idx = tid + i * 512;
        int row = idx >> 5, c4 = idx & 31;
        float4 v = make_float4(0.f, 0.f, 0.f, 0.f);
        int grow = rowBase + row;
        if (grow < N) v = *(const float4*)(g_h + (size_t)grow * HIDDEN + c4 * 4);
        int c = c4 * 4;
        As[row * AS_STRIDE + phys8(c + 0)] = f2tf_f(v.x);
        As[row * AS_STRIDE + phys8(c + 1)] = f2tf_f(v.y);
        As[row * AS_STRIDE + phys8(c + 2)] = f2tf_f(v.z);
        As[row * AS_STRIDE + phys8(c + 3)] = f2tf_f(v.w);
    }

    const float* w_up  = g_w;
    const float* w_lin = g_w + HIDDEN * OUT_EMB;

    do_layer<128, 0>(As, W0s, W1s, w0a, w1a, w_up,              nullptr,     nullptr, nullptr, wm, wn, lane, tid);
    do_layer<256, 1>(As, W0s, W1s, w0a, w1a, w_lin,             sbias,       nullptr, nullptr, wm, wn, lane, tid);
    do_layer<256, 1>(As, W0s, W1s, w0a, w1a, w_lin + 65536,     sbias + 256, nullptr, nullptr, wm, wn, lane, tid);
    do_layer<256, 2>(As, W0s, W1s, w0a, w1a, w_lin + 2 * 65536, sbias + 512, swout,   fpart,   wm, wn, lane, tid);

    __syncthreads();
    if (tid < 128) {
        float s = fpart[tid] + fpart[tid + 128] + fpart[tid + 256] + fpart[tid + 384];
        int grow = rowBase + tid;
        if (grow < N) out[grow] = s;
    }
}

// ================= launch =================
extern "C" void kernel_launch(void* const* d_in, const int* in_sizes, int n_in,
                              void* d_out, int out_size) {
    const float* x   = (const float*)d_in[0];
    const float* rbf = (const float*)d_in[1];
    const int*   ei  = (const int*)d_in[2];

    int wi = 3;
    while (wi < n_in && in_sizes[wi] != HIDDEN * NUM_RADIAL) wi++;
    const float* W_rbf  = (const float*)d_in[wi + 0];
    const float* W_up   = (const float*)d_in[wi + 1];
    const float* lins_w = (const float*)d_in[wi + 2];
    const float* lins_b = (const float*)d_in[wi + 3];
    const float* W_out  = (const float*)d_in[wi + 4];
    float* out = (float*)d_out;

    int E = in_sizes[0] / HIDDEN;
    if (E > MAX_EDGES) E = MAX_EDGES;
    int N = out_size < MAX_NODES ? out_size : MAX_NODES;

    const int SMEM_BYTES = F_TOTAL * (int)sizeof(float);   // 223232
    cudaFuncSetAttribute(mlp_kernel, cudaFuncAttributeMaxDynamicSharedMemorySize, SMEM_BYTES);
    const int GSMEM = 8 * (G_DEPTH * G_EPB * 512) + 8 * (G_DEPTH * G_EPB * 32);   // 52224
    cudaFuncSetAttribute(gather_kernel, cudaFuncAttributeMaxDynamicSharedMemorySize, GSMEM);

    int eb = (E + 255) / 256;
    int sb = (N + 1023) / 1024;
    int prep_total = HIDDEN * OUT_EMB + 3 * OUT_EMB * OUT_EMB;
    int ib = (prep_total > N ? prep_total : N);

    init_kernel<<<(ib + 255) / 256, 256>>>(W_up, lins_w, N);
    hist_kernel<<<eb, 256>>>(ei, E, N);
    scan1_kernel<<<sb, 1024>>>(N);
    scan2_kernel<<<sb, 1024>>>(N, sb);
    scatter_kernel<<<eb, 256>>>(ei, E, N);
    gather_kernel<<<(N + 7) / 8, 256, GSMEM>>>(x, rbf, W_rbf, N);

    int mblocks = (N + 127) / 128;
    mlp_kernel<<<mblocks, 512, SMEM_BYTES>>>(lins_b, W_out, out, N);
}

// round 12
// speedup vs baseline: 1.0637x; 1.0637x over previous
#include <cuda_runtime.h>
#include <cuda_bf16.h>
#include <cstdint>

// ---------------- problem constants ----------------
#define HIDDEN      128
#define NUM_RADIAL  6
#define OUT_EMB     256
#define MAX_NODES   50000
#define MAX_EDGES   1600000

#define AS_STRIDE   260
#define WS_STRIDE   36

// gather pipeline
#define G_DEPTH 3
#define G_EPB   4

// ---------------- device scratch ----------------
__device__ float g_h[(size_t)MAX_NODES * HIDDEN];
__device__ float g_w[HIDDEN * OUT_EMB + 3 * OUT_EMB * OUT_EMB];
__device__ int   g_cnt[MAX_NODES];
__device__ int   g_start[MAX_NODES];
__device__ int   g_cursor[MAX_NODES];
__device__ int   g_eid[MAX_EDGES];
__device__ int   g_blksum[64];

// ---------------- helpers ----------------
__device__ __forceinline__ uint32_t smem_u32(const void* p) {
    uint32_t a;
    asm("{ .reg .u64 t; cvta.to.shared.u64 t, %1; cvt.u32.u64 %0, t; }" : "=r"(a) : "l"(p));
    return a;
}
__device__ __forceinline__ uint32_t f2tf(float x) {
    uint32_t r; asm("cvt.rna.tf32.f32 %0, %1;" : "=r"(r) : "f"(x)); return r;
}
__device__ __forceinline__ float f2tf_f(float x) { return __uint_as_float(f2tf(x)); }
__device__ __forceinline__ void mma8(float* d, const uint32_t* a, uint32_t b0, uint32_t b1) {
    asm volatile("mma.sync.aligned.m16n8k8.row.col.f32.tf32.tf32.f32 "
                 "{%0,%1,%2,%3}, {%4,%5,%6,%7}, {%8,%9}, {%0,%1,%2,%3};"
                 : "+f"(d[0]), "+f"(d[1]), "+f"(d[2]), "+f"(d[3])
                 : "r"(a[0]), "r"(a[1]), "r"(a[2]), "r"(a[3]), "r"(b0), "r"(b1));
}
__device__ __forceinline__ void cp16(uint32_t s, const float* g) {
    asm volatile("cp.async.cg.shared.global [%0], [%1], 16;" :: "r"(s), "l"(g));
}
__device__ __forceinline__ void cp8(uint32_t s, const float* g) {
    asm volatile("cp.async.ca.shared.global [%0], [%1], 8;" :: "r"(s), "l"(g));
}
#define CP_COMMIT() asm volatile("cp.async.commit_group;")
#define CP_WAIT(n)  asm volatile("cp.async.wait_group %0;" :: "n"(n))

// ================= CSR build =================
__global__ void __launch_bounds__(256) init_kernel(const float* __restrict__ W_up,
                                                   const float* __restrict__ lins_w, int N) {
    int gid = blockIdx.x * 256 + threadIdx.x;
    if (gid < N) g_cnt[gid] = 0;
    const int NW_UP = HIDDEN * OUT_EMB;
    const int NW_ALL = NW_UP + 3 * OUT_EMB * OUT_EMB;
    if (gid < NW_UP)       g_w[gid] = f2tf_f(W_up[gid]);
    else if (gid < NW_ALL) g_w[gid] = f2tf_f(lins_w[gid - NW_UP]);
}

__global__ void __launch_bounds__(256) hist_kernel(const int* __restrict__ ei, int E, int N) {
    int e = blockIdx.x * 256 + threadIdx.x;
    if (e < E) {
        int node = __ldg(ei + e);
        if (node >= 0 && node < N) atomicAdd(&g_cnt[node], 1);
    }
}

__global__ void __launch_bounds__(1024) scan1_kernel(int N) {
    __shared__ int sw[32];
    int tid = threadIdx.x;
    int i = blockIdx.x * 1024 + tid;
    int v = (i < N) ? g_cnt[i] : 0;
#pragma unroll
    for (int o = 16; o; o >>= 1) v += __shfl_xor_sync(0xffffffffu, v, o);
    if ((tid & 31) == 0) sw[tid >> 5] = v;
    __syncthreads();
    if (tid < 32) {
        int s = sw[tid];
#pragma unroll
        for (int o = 16; o; o >>= 1) s += __shfl_xor_sync(0xffffffffu, s, o);
        if (tid == 0) g_blksum[blockIdx.x] = s;
    }
}

__global__ void __launch_bounds__(1024) scan2_kernel(int N, int nb) {
    __shared__ int swarp[32];
    __shared__ int sb2[2];
    int tid = threadIdx.x, lane = tid & 31, wid = tid >> 5;

    if (tid < 64) {
        int c = (tid < nb && tid < blockIdx.x) ? g_blksum[tid] : 0;
#pragma unroll
        for (int o = 16; o; o >>= 1) c += __shfl_xor_sync(0xffffffffu, c, o);
        if (lane == 0) sb2[wid] = c;
    }

    int i = blockIdx.x * 1024 + tid;
    int v = (i < N) ? g_cnt[i] : 0;
    int xi = v;
#pragma unroll
    for (int o = 1; o < 32; o <<= 1) {
        int y = __shfl_up_sync(0xffffffffu, xi, o);
        if (lane >= o) xi += y;
    }
    if (lane == 31) swarp[wid] = xi;
    __syncthreads();
    if (wid == 0) {
        int s = swarp[lane];
#pragma unroll
        for (int o = 1; o < 32; o <<= 1) {
            int y = __shfl_up_sync(0xffffffffu, s, o);
            if (lane >= o) s += y;
        }
        swarp[lane] = s;
    }
    __syncthreads();
    int woff = (wid == 0) ? 0 : swarp[wid - 1];
    int excl = woff + xi - v;
    int boff = sb2[0] + sb2[1];
    if (i < N) { g_start[i] = boff + excl; g_cursor[i] = boff + excl; }
}

__global__ void __launch_bounds__(256) scatter_kernel(const int* __restrict__ ei, int E, int N) {
    int e = blockIdx.x * 256 + threadIdx.x;
    if (e < E) {
        int node = __ldg(ei + e);
        if (node >= 0 && node < N) {
            int pos = atomicAdd(&g_cursor[node], 1);
            g_eid[pos] = e;
        }
    }
}

// ================= gather: cp.async smem pipeline, 1 warp/node =================
__global__ void __launch_bounds__(256) gather_kernel(const float* __restrict__ x,
                                                     const float* __restrict__ rbf,
                                                     const float* __restrict__ W_rbf,
                                                     int N) {
    extern __shared__ char gsm[];
    const int tid = threadIdx.x;
    const int lane = tid & 31;
    const int w = tid >> 5;
    const int node = blockIdx.x * 8 + w;

    char* xw = gsm + w * (G_DEPTH * G_EPB * 512);
    float* rw = (float*)(gsm + 8 * (G_DEPTH * G_EPB * 512) + w * (G_DEPTH * G_EPB * 32));
    const uint32_t xs_base = smem_u32(xw);
    const uint32_t rs_base = smem_u32(rw);

    float4 wc[NUM_RADIAL];
#pragma unroll
    for (int r = 0; r < NUM_RADIAL; r++) {
        wc[r].x = __ldg(W_rbf + (lane * 4 + 0) * NUM_RADIAL + r);
        wc[r].y = __ldg(W_rbf + (lane * 4 + 1) * NUM_RADIAL + r);
        wc[r].z = __ldg(W_rbf + (lane * 4 + 2) * NUM_RADIAL + r);
        wc[r].w = __ldg(W_rbf + (lane * 4 + 3) * NUM_RADIAL + r);
    }

    int start = 0, cnt = 0;
    if (node < N) { start = __ldg(&g_start[node]); cnt = __ldg(&g_cnt[node]); }

    float4 acc = make_float4(0.f, 0.f, 0.f, 0.f);
    const int nb = (cnt + G_EPB - 1) / G_EPB;
    int e_l = 0;

    for (int b = 0; b < nb + 2; b++) {
        if (b < nb) {
            if ((b & 7) == 0) {
                int idx = b * G_EPB + lane;
                e_l = (idx < cnt) ? __ldg(g_eid + start + idx) : 0;
            }
            const int d = b % G_DEPTH;
            const int sh = (b & 7) * G_EPB;
#pragma unroll
            for (int i = 0; i < G_EPB; i++) {
                int e = __shfl_sync(0xffffffffu, e_l, sh + i);
                cp16(xs_base + (d * G_EPB + i) * 512 + lane * 16,
                     x + (size_t)e * HIDDEN + lane * 4);
                if (lane < 3)
                    cp8(rs_base + ((d * G_EPB + i) * 8 + lane * 2) * 4,
                        rbf + (size_t)e * NUM_RADIAL + lane * 2);
            }
        }
        CP_COMMIT();
        if (b >= 2) {
            CP_WAIT(2);
            __syncwarp();
            const int cb = b - 2;
            const int d = cb % G_DEPTH;
            const int ebase = cb * G_EPB;
#pragma unroll
            for (int i = 0; i < G_EPB; i++) {
                if (ebase + i < cnt) {
                    const float* rp = rw + (d * G_EPB + i) * 8;
                    float4 xv = *(const float4*)(xw + (d * G_EPB + i) * 512 + lane * 16);
                    float r0 = rp[0], r1 = rp[1], r2 = rp[2];
                    float r3 = rp[3], r4 = rp[4], r5 = rp[5];
                    float4 p;
                    p.x = r0 * wc[0].x; p.y = r0 * wc[0].y; p.z = r0 * wc[0].z; p.w = r0 * wc[0].w;
                    p.x = fmaf(r1, wc[1].x, p.x); p.y = fmaf(r1, wc[1].y, p.y);
                    p.z = fmaf(r1, wc[1].z, p.z); p.w = fmaf(r1, wc[1].w, p.w);
                    p.x = fmaf(r2, wc[2].x, p.x); p.y = fmaf(r2, wc[2].y, p.y);
                    p.z = fmaf(r2, wc[2].z, p.z); p.w = fmaf(r2, wc[2].w, p.w);
                    p.x = fmaf(r3, wc[3].x, p.x); p.y = fmaf(r3, wc[3].y, p.y);
                    p.z = fmaf(r3, wc[3].z, p.z); p.w = fmaf(r3, wc[3].w, p.w);
                    p.x = fmaf(r4, wc[4].x, p.x); p.y = fmaf(r4, wc[4].y, p.y);
                    p.z = fmaf(r4, wc[4].z, p.z); p.w = fmaf(r4, wc[4].w, p.w);
                    p.x = fmaf(r5, wc[5].x, p.x); p.y = fmaf(r5, wc[5].y, p.y);
                    p.z = fmaf(r5, wc[5].z, p.z); p.w = fmaf(r5, wc[5].w, p.w);
                    acc.x = fmaf(p.x, xv.x, acc.x); acc.y = fmaf(p.y, xv.y, acc.y);
                    acc.z = fmaf(p.z, xv.z, acc.z); acc.w = fmaf(p.w, xv.w, acc.w);
                }
            }
        }
    }

    if (node < N)
        *(float4*)(g_h + (size_t)node * HIDDEN + lane * 4) = acc;
}

// ================= MLP via mma.sync tf32: 128-row tiles, 64x64 warp tiles =================
// 256 thr = 8 warps = 2(m) x 4(n); warp tile 64 rows x 64 cols; d[4][8][4] = 128 regs.
// Per k8 per warp: 16 A + 16 B smem values feed 32 HMMA (crossbar-balanced).
template<int K, int MODE>
__device__ __forceinline__ void do_layer(float* __restrict__ As,
                                         const float* __restrict__ W0s,
                                         const float* __restrict__ W1s,
                                         uint32_t w0a, uint32_t w1a,
                                         const float* __restrict__ Wg,
                                         const float* __restrict__ bias,
                                         const float* __restrict__ wout,
                                         float* __restrict__ fpart,
                                         int wm, int wn, int lane, int tid) {
    constexpr int NC = K / 32;
    float d[4][8][4];
#pragma unroll
    for (int m = 0; m < 4; m++)
#pragma unroll
        for (int n = 0; n < 8; n++)
#pragma unroll
            for (int j = 0; j < 4; j++) d[m][n][j] = 0.f;

    // stage chunk 0: 256 rows x 32 k, 256 threads -> 8 cp16 each
    {
#pragma unroll
        for (int i = 0; i < 8; i++) {
            int idx = tid + i * 256;
            int row = idx >> 3, q = idx & 7;
            cp16(w0a + (uint32_t)(row * WS_STRIDE + q * 4) * 4, Wg + (size_t)row * K + q * 4);
        }
        CP_COMMIT();
    }

    for (int c = 0; c < NC; c++) {
        __syncthreads();
        if (c + 1 < NC) {
            uint32_t na = ((c + 1) & 1) ? w1a : w0a;
#pragma unroll
            for (int i = 0; i < 8; i++) {
                int idx = tid + i * 256;
                int row = idx >> 3, q = idx & 7;
                cp16(na + (uint32_t)(row * WS_STRIDE + q * 4) * 4,
                     Wg + (size_t)row * K + (c + 1) * 32 + q * 4);
            }
            CP_COMMIT();
            CP_WAIT(1);
        } else {
            CP_WAIT(0);
        }
        __syncthreads();

        const float* Ws = (c & 1) ? W1s : W0s;
        const int kb0 = c * 32;
#pragma unroll
        for (int k8 = 0; k8 < 4; k8++) {
            const int kb = kb0 + k8 * 8;
            uint32_t ah[4][4];
#pragma unroll
            for (int m = 0; m < 4; m++) {
                int r = wm * 64 + m * 16 + (lane >> 2);
                const float* ap = As + r * AS_STRIDE + kb + (lane & 3);
                ah[m][0] = __float_as_uint(ap[0]);
                ah[m][1] = __float_as_uint(ap[8 * AS_STRIDE]);
                ah[m][2] = __float_as_uint(ap[4]);
                ah[m][3] = __float_as_uint(ap[8 * AS_STRIDE + 4]);
            }
#pragma unroll
            for (int n = 0; n < 8; n++) {
                int coln = wn * 64 + n * 8 + (lane >> 2);
                const float* bp = Ws + coln * WS_STRIDE + k8 * 8 + (lane & 3);
                uint32_t b0 = __float_as_uint(bp[0]);
                uint32_t b1 = __float_as_uint(bp[4]);
#pragma unroll
                for (int m = 0; m < 4; m++)
                    mma8(d[m][n], ah[m], b0, b1);
            }
        }
    }

    if (MODE != 2) {
        __syncthreads();
#pragma unroll
        for (int m = 0; m < 4; m++) {
            int r = wm * 64 + m * 16 + (lane >> 2);
#pragma unroll
            for (int n = 0; n < 8; n++) {
                int col = wn * 64 + n * 8 + (lane & 3) * 2;
                float v0 = d[m][n][0], v1 = d[m][n][1];
                float v2 = d[m][n][2], v3 = d[m][n][3];
                if (MODE == 1) {
                    float b0 = bias[col], b1 = bias[col + 1];
                    v0 = fmaxf(v0 + b0, 0.f); v1 = fmaxf(v1 + b1, 0.f);
                    v2 = fmaxf(v2 + b0, 0.f); v3 = fmaxf(v3 + b1, 0.f);
                }
                v0 = f2tf_f(v0); v1 = f2tf_f(v1); v2 = f2tf_f(v2); v3 = f2tf_f(v3);
                *(float2*)(As + r * AS_STRIDE + col)       = make_float2(v0, v1);
                *(float2*)(As + (r + 8) * AS_STRIDE + col) = make_float2(v2, v3);
            }
        }
        __syncthreads();
    } else {
        float s[4][2];
#pragma unroll
        for (int m = 0; m < 4; m++) { s[m][0] = 0.f; s[m][1] = 0.f; }
#pragma unroll
        for (int m = 0; m < 4; m++)
#pragma unroll
            for (int n = 0; n < 8; n++) {
                int col = wn * 64 + n * 8 + (lane & 3) * 2;
                float b0 = bias[col], b1 = bias[col + 1];
                float w0 = wout[col], w1 = wout[col + 1];
                float v0 = fmaxf(d[m][n][0] + b0, 0.f);
                float v1 = fmaxf(d[m][n][1] + b1, 0.f);
                float v2 = fmaxf(d[m][n][2] + b0, 0.f);
                float v3 = fmaxf(d[m][n][3] + b1, 0.f);
                s[m][0] = fmaf(v0, w0, fmaf(v1, w1, s[m][0]));
                s[m][1] = fmaf(v2, w0, fmaf(v3, w1, s[m][1]));
            }
#pragma unroll
        for (int m = 0; m < 4; m++)
#pragma unroll
            for (int h = 0; h < 2; h++) {
                float v = s[m][h];
                v += __shfl_xor_sync(0xffffffffu, v, 1);
                v += __shfl_xor_sync(0xffffffffu, v, 2);
                s[m][h] = v;
            }
        if ((lane & 3) == 0) {
#pragma unroll
            for (int m = 0; m < 4; m++) {
                int rbase = wm * 64 + m * 16 + (lane >> 2);
                fpart[wn * 128 + rbase]     = s[m][0];
                fpart[wn * 128 + rbase + 8] = s[m][1];
            }
        }
    }
}

// smem float offsets (same as R10: 212992 B)
#define F_AS    0
#define F_W0    33280
#define F_W1    (33280 + 9216)
#define F_BIAS  (33280 + 2 * 9216)
#define F_WOUT  (F_BIAS + 768)
#define F_FPART (F_WOUT + 256)
#define F_TOTAL (F_FPART + 512)

__global__ void __launch_bounds__(256, 1) mlp_kernel(const float* __restrict__ lins_b,
                                                     const float* __restrict__ W_out,
                                                     float* __restrict__ out, int N) {
    extern __shared__ float smem[];
    float* As    = smem + F_AS;
    float* W0s   = smem + F_W0;
    float* W1s   = smem + F_W1;
    float* sbias = smem + F_BIAS;
    float* swout = smem + F_WOUT;
    float* fpart = smem + F_FPART;
    uint32_t w0a = smem_u32(W0s), w1a = smem_u32(W1s);

    const int tid = threadIdx.x;
    const int lane = tid & 31;
    const int wid = tid >> 5;
    const int wm = wid & 1;       // 2 m-groups of 64 rows
    const int wn = wid >> 1;      // 4 n-groups of 64 cols
    const int rowBase = blockIdx.x * 128;

    for (int t = tid; t < 768; t += 256) sbias[t] = lins_b[t];
    if (tid < 256) swout[tid] = W_out[tid];

    // load A (g_h[128 rows x 128 cols]), tf32-round
#pragma unroll
    for (int i = 0; i < 16; i++) {
        int idx = tid + i * 256;
        int row = idx >> 5, c4 = idx & 31;
        float4 v = make_float4(0.f, 0.f, 0.f, 0.f);
        int grow = rowBase + row;
        if (grow < N) v = *(const float4*)(g_h + (size_t)grow * HIDDEN + c4 * 4);
        v.x = f2tf_f(v.x); v.y = f2tf_f(v.y); v.z = f2tf_f(v.z); v.w = f2tf_f(v.w);
        *(float4*)(As + row * AS_STRIDE + c4 * 4) = v;
    }

    const float* w_up  = g_w;
    const float* w_lin = g_w + HIDDEN * OUT_EMB;

    do_layer<128, 0>(As, W0s, W1s, w0a, w1a, w_up,              nullptr,     nullptr, nullptr, wm, wn, lane, tid);
    do_layer<256, 1>(As, W0s, W1s, w0a, w1a, w_lin,             sbias,       nullptr, nullptr, wm, wn, lane, tid);
    do_layer<256, 1>(As, W0s, W1s, w0a, w1a, w_lin + 65536,     sbias + 256, nullptr, nullptr, wm, wn, lane, tid);
    do_layer<256, 2>(As, W0s, W1s, w0a, w1a, w_lin + 2 * 65536, sbias + 512, swout,   fpart,   wm, wn, lane, tid);

    __syncthreads();
    if (tid < 128) {
        float s = fpart[tid] + fpart[tid + 128] + fpart[tid + 256] + fpart[tid + 384];
        int grow = rowBase + tid;
        if (grow < N) out[grow] = s;
    }
}

// ================= launch =================
extern "C" void kernel_launch(void* const* d_in, const int* in_sizes, int n_in,
                              void* d_out, int out_size) {
    const float* x   = (const float*)d_in[0];
    const float* rbf = (const float*)d_in[1];
    const int*   ei  = (const int*)d_in[2];

    int wi = 3;
    while (wi < n_in && in_sizes[wi] != HIDDEN * NUM_RADIAL) wi++;
    const float* W_rbf  = (const float*)d_in[wi + 0];
    const float* W_up   = (const float*)d_in[wi + 1];
    const float* lins_w = (const float*)d_in[wi + 2];
    const float* lins_b = (const float*)d_in[wi + 3];
    const float* W_out  = (const float*)d_in[wi + 4];
    float* out = (float*)d_out;

    int E = in_sizes[0] / HIDDEN;
    if (E > MAX_EDGES) E = MAX_EDGES;
    int N = out_size < MAX_NODES ? out_size : MAX_NODES;

    const int SMEM_BYTES = F_TOTAL * (int)sizeof(float);   // 212992
    cudaFuncSetAttribute(mlp_kernel, cudaFuncAttributeMaxDynamicSharedMemorySize, SMEM_BYTES);
    const int GSMEM = 8 * (G_DEPTH * G_EPB * 512) + 8 * (G_DEPTH * G_EPB * 32);   // 52224
    cudaFuncSetAttribute(gather_kernel, cudaFuncAttributeMaxDynamicSharedMemorySize, GSMEM);

    int eb = (E + 255) / 256;
    int sb = (N + 1023) / 1024;
    int prep_total = HIDDEN * OUT_EMB + 3 * OUT_EMB * OUT_EMB;
    int ib = (prep_total > N ? prep_total : N);

    init_kernel<<<(ib + 255) / 256, 256>>>(W_up, lins_w, N);
    hist_kernel<<<eb, 256>>>(ei, E, N);
    scan1_kernel<<<sb, 1024>>>(N);
    scan2_kernel<<<sb, 1024>>>(N, sb);
    scatter_kernel<<<eb, 256>>>(ei, E, N);
    gather_kernel<<<(N + 7) / 8, 256, GSMEM>>>(x, rbf, W_rbf, N);

    int mblocks = (N + 127) / 128;
    mlp_kernel<<<mblocks, 256, SMEM_BYTES>>>(lins_b, W_out, out, N);
}